// round 12
// baseline (speedup 1.0000x reference)
#include <cuda_runtime.h>
#include <cstddef>

// Problem dims (fixed by the dataset)
#define B_   8192
#define T_   25
#define D0_  100
#define H1_  100
#define H2_  400
#define O_   784

// Persistent state in device globals (no allocations allowed)
__device__ float g_m1[B_ * H1_];
__device__ float g_m2[B_ * H2_];
__device__ float g_m3[B_ * O_];
__device__ float g_s1[B_ * H1_];
__device__ float g_s2[B_ * H2_];
// Split-K partial buffers for layer 1
__device__ float g_p0[B_ * H1_];
__device__ float g_p1[B_ * H1_];

__global__ void zero_membranes() {
    long long i = (long long)blockIdx.x * blockDim.x + threadIdx.x;
    long long stride = (long long)gridDim.x * blockDim.x;
    const long long n1 = (long long)B_ * H1_;
    const long long n2 = (long long)B_ * H2_;
    const long long n3 = (long long)B_ * O_;
    for (long long k = i; k < n1; k += stride) g_m1[k] = 0.0f;
    for (long long k = i; k < n2; k += stride) g_m2[k] = 0.0f;
    for (long long k = i; k < n3; k += stride) g_m3[k] = 0.0f;
}

#define BM 64
#define BN 64
#define BK 16

// Plain GEMM partial over k in [kbeg, kend): fold-left FMA chain, ascending k,
// single accumulator, zero-pad neutral. Writes raw partial sums (no epilogue).
__global__ __launch_bounds__(256)
void gemm_partial(const float* __restrict__ A, int lda,
                  const float* __restrict__ W,
                  float* __restrict__ out,
                  int M, int N, int K, int kbeg, int kend)
{
    __shared__ float As[BK][BM + 4];
    __shared__ float Ws[BK][BN + 4];

    const int tid  = threadIdx.x;
    const int tcol = tid & 15;
    const int trow = tid >> 4;
    const int n0 = blockIdx.x * BN;
    const int m0 = blockIdx.y * BM;
    const int lk = tid & 15;
    const int lr = tid >> 4;

    float acc[4][4];
    #pragma unroll
    for (int i = 0; i < 4; i++)
        #pragma unroll
        for (int j = 0; j < 4; j++)
            acc[i][j] = 0.0f;

    for (int k0 = kbeg; k0 < kend; k0 += BK) {
        const int k = k0 + lk;
        const bool kok = (k < kend) && (k < K);
        #pragma unroll
        for (int r = 0; r < 4; r++) {
            const int m = m0 + lr + 16 * r;
            As[lk][lr + 16 * r] = (kok && m < M) ? A[(size_t)m * lda + k] : 0.0f;
            const int n = n0 + lr + 16 * r;
            Ws[lk][lr + 16 * r] = (kok && n < N) ? W[(size_t)n * K + k] : 0.0f;
        }
        __syncthreads();
        #pragma unroll
        for (int kk = 0; kk < BK; kk++) {
            float4 av = *reinterpret_cast<const float4*>(&As[kk][trow * 4]);
            float4 wv = *reinterpret_cast<const float4*>(&Ws[kk][tcol * 4]);
            float a[4] = {av.x, av.y, av.z, av.w};
            float w[4] = {wv.x, wv.y, wv.z, wv.w};
            #pragma unroll
            for (int i = 0; i < 4; i++)
                #pragma unroll
                for (int j = 0; j < 4; j++)
                    acc[i][j] = __fmaf_rn(a[i], w[j], acc[i][j]);
        }
        __syncthreads();
    }

    #pragma unroll
    for (int i = 0; i < 4; i++) {
        const int row = m0 + trow * 4 + i;
        if (row >= M) continue;
        #pragma unroll
        for (int j = 0; j < 4; j++) {
            const int col = n0 + tcol * 4 + j;
            if (col >= N) continue;
            out[(size_t)row * N + col] = acc[i][j];
        }
    }
}

// Combine split-K partials (ascending order) + LIF epilogue (contracted fma form).
__global__ __launch_bounds__(256)
void combine_lif(const float* __restrict__ P0,
                 const float* __restrict__ P1,
                 const float* __restrict__ bias,
                 float* __restrict__ mbuf,
                 float* __restrict__ spk, int spk_stride,
                 int M, int N)
{
    long long idx = (long long)blockIdx.x * blockDim.x + threadIdx.x;
    long long total = (long long)M * N;
    if (idx >= total) return;
    const int row = (int)(idx / N);
    const int col = (int)(idx - (long long)row * N);

    float acc = __fadd_rn(P0[idx], P1[idx]);        // split combine, s ascending
    float pre = __fadd_rn(acc, bias[col]);
    float cur = fmaxf(__fmul_rn(2.0f, pre), 0.0f);
    float mp  = mbuf[idx];
    float rst = (mp > 1.0f) ? 1.0f : 0.0f;
    float mn  = __fsub_rn(__fmaf_rn(0.95f, mp, cur), rst);   // contracted epilogue
    mbuf[idx] = mn;
    spk[(size_t)row * spk_stride + col] = (mn > 1.0f) ? 1.0f : 0.0f;
}

// Fused fold-left GEMM + LIF (layers 2/3): FMA chain ascending k, contracted epilogue.
__global__ __launch_bounds__(256)
void gemm_lif(const float* __restrict__ A, int lda,
              const float* __restrict__ W,
              const float* __restrict__ bias,
              float* __restrict__ mbuf,
              float* __restrict__ spk, int spk_stride,
              int M, int N, int K)
{
    __shared__ float As[BK][BM + 4];
    __shared__ float Ws[BK][BN + 4];

    const int tid  = threadIdx.x;
    const int tcol = tid & 15;
    const int trow = tid >> 4;
    const int n0 = blockIdx.x * BN;
    const int m0 = blockIdx.y * BM;
    const int lk = tid & 15;
    const int lr = tid >> 4;

    float acc[4][4];
    #pragma unroll
    for (int i = 0; i < 4; i++)
        #pragma unroll
        for (int j = 0; j < 4; j++)
            acc[i][j] = 0.0f;

    for (int k0 = 0; k0 < K; k0 += BK) {
        const int k = k0 + lk;
        const bool kok = (k < K);
        #pragma unroll
        for (int r = 0; r < 4; r++) {
            const int m = m0 + lr + 16 * r;
            As[lk][lr + 16 * r] = (kok && m < M) ? A[(size_t)m * lda + k] : 0.0f;
            const int n = n0 + lr + 16 * r;
            Ws[lk][lr + 16 * r] = (kok && n < N) ? W[(size_t)n * K + k] : 0.0f;
        }
        __syncthreads();
        #pragma unroll
        for (int kk = 0; kk < BK; kk++) {
            float4 av = *reinterpret_cast<const float4*>(&As[kk][trow * 4]);
            float4 wv = *reinterpret_cast<const float4*>(&Ws[kk][tcol * 4]);
            float a[4] = {av.x, av.y, av.z, av.w};
            float w[4] = {wv.x, wv.y, wv.z, wv.w};
            #pragma unroll
            for (int i = 0; i < 4; i++)
                #pragma unroll
                for (int j = 0; j < 4; j++)
                    acc[i][j] = __fmaf_rn(a[i], w[j], acc[i][j]);
        }
        __syncthreads();
    }

    #pragma unroll
    for (int i = 0; i < 4; i++) {
        const int row = m0 + trow * 4 + i;
        if (row >= M) continue;
        #pragma unroll
        for (int j = 0; j < 4; j++) {
            const int col = n0 + tcol * 4 + j;
            if (col >= N) continue;
            float pre = __fadd_rn(acc[i][j], bias[col]);
            float cur = fmaxf(__fmul_rn(2.0f, pre), 0.0f);
            const size_t midx = (size_t)row * N + col;
            float mp  = mbuf[midx];
            float rst = (mp > 1.0f) ? 1.0f : 0.0f;
            float mn  = __fsub_rn(__fmaf_rn(0.95f, mp, cur), rst);  // contracted
            mbuf[midx] = mn;
            spk[(size_t)row * spk_stride + col] = (mn > 1.0f) ? 1.0f : 0.0f;
        }
    }
}

extern "C" void kernel_launch(void* const* d_in, const int* in_sizes, int n_in,
                              void* d_out, int out_size)
{
    (void)in_sizes; (void)n_in; (void)out_size;
    const float* x  = (const float*)d_in[0];
    const float* W1 = (const float*)d_in[1];
    const float* b1 = (const float*)d_in[2];
    const float* W2 = (const float*)d_in[3];
    const float* b2 = (const float*)d_in[4];
    const float* W3 = (const float*)d_in[5];
    const float* b3 = (const float*)d_in[6];
    float* out = (float*)d_out;

    void* p;
    cudaGetSymbolAddress(&p, g_m1); float* m1 = (float*)p;
    cudaGetSymbolAddress(&p, g_m2); float* m2 = (float*)p;
    cudaGetSymbolAddress(&p, g_m3); float* m3 = (float*)p;
    cudaGetSymbolAddress(&p, g_s1); float* s1 = (float*)p;
    cudaGetSymbolAddress(&p, g_s2); float* s2 = (float*)p;
    cudaGetSymbolAddress(&p, g_p0); float* p0 = (float*)p;
    cudaGetSymbolAddress(&p, g_p1); float* p1 = (float*)p;

    zero_membranes<<<1024, 256>>>();

    const dim3 thr(256);
    const dim3 grid1((H1_ + BN - 1) / BN, B_ / BM);   // (2, 128)
    const dim3 grid2((H2_ + BN - 1) / BN, B_ / BM);   // (7, 128)
    const dim3 grid3((O_  + BN - 1) / BN, B_ / BM);   // (13, 128)
    const int KSPLIT = 64;                            // split-K=2 boundary (k-tile 16/32)
    const int combine_blocks = (B_ * H1_ + 255) / 256;

    for (int t = 0; t < T_; t++) {
        // Layer 1: split-K = 2 (partials in ascending split order), then combine+LIF
        gemm_partial<<<grid1, thr>>>(x + (size_t)t * D0_, T_ * D0_, W1, p0,
                                     B_, H1_, D0_, 0, KSPLIT);
        gemm_partial<<<grid1, thr>>>(x + (size_t)t * D0_, T_ * D0_, W1, p1,
                                     B_, H1_, D0_, KSPLIT, D0_);
        combine_lif<<<combine_blocks, thr>>>(p0, p1, b1, m1, s1, H1_, B_, H1_);
        // Layers 2/3: plain fold-left
        gemm_lif<<<grid2, thr>>>(s1, H1_, W2, b2, m2, s2, H2_,
                                 B_, H2_, H1_);
        gemm_lif<<<grid3, thr>>>(s2, H2_, W3, b3, m3, out + (size_t)t * O_, T_ * O_,
                                 B_, O_, H2_);
    }
}